// round 13
// baseline (speedup 1.0000x reference)
#include <cuda_runtime.h>
#include <cuda_fp16.h>
#include <cstdint>

// ============================================================================
// DigitConvolutionalModel: out = relu(conv3x3(x) @ w1 + b1) @ w2 + b2
// Folded:  out = relu(x @ W1eff + b1) @ w2 + b2,   W1eff = C @ w1   [784,128]
//
// R11: warp-specialized producer/consumer pipeline.
//  512 threads: warps 0-7 consumers (ldmatrix+mma only),
//               warps 8-15 producers (LDG A fp32->cvt->STS fp16, cp.async B).
//  4-stage smem ring, named full/empty barriers. 1 CTA/SM.
// ============================================================================

#define B_ROWS   65536
#define K_REAL   784
#define NCH      13          // 13 * 64 = 832 >= 784 (chunk 12 zero-padded)
#define BM       64
#define THREADS  512
#define NSTAGE   4

// named barrier ids (0 reserved for __syncthreads)
#define FULL0    1
#define EMPTY0   5

// ---- dynamic smem layout ----
#define STAGE_BYTES 24576      // A16 8KB + B 16KB
#define A16_OFF     0
#define B_OFF       8192
#define SM_B1       98304      // 128 fp32
#define SM_W2       98816      // 1280 fp32
#define SM_PACC     103936     // 640 fp32
#define SMEM_TOTAL  106496     // 104 KB

// Pre-swizzled W1eff^T tiles: [chunk64][128n x 64k] fp16 (chunk 12 zero-padded).
__device__ __align__(16) __half g_B[NCH][128 * 64];

// -------------------- helpers --------------------
__device__ __forceinline__ uint32_t smem_u32(const void* p) {
    uint32_t a;
    asm("{ .reg .u64 t; cvta.to.shared.u64 t, %1; cvt.u32.u64 %0, t; }" : "=r"(a) : "l"(p));
    return a;
}
__device__ __forceinline__ uint32_t sw128(uint32_t off) {
    return off ^ ((off >> 3) & 0x70);
}
__device__ __forceinline__ void cp_async16(uint32_t dst, const void* src) {
    asm volatile("cp.async.cg.shared.global [%0], [%1], 16;" :: "r"(dst), "l"(src) : "memory");
}
__device__ __forceinline__ void ldmatrix_x4(uint32_t& d0, uint32_t& d1, uint32_t& d2,
                                            uint32_t& d3, uint32_t addr) {
    asm volatile("ldmatrix.sync.aligned.m8n8.x4.shared.b16 {%0,%1,%2,%3}, [%4];"
                 : "=r"(d0), "=r"(d1), "=r"(d2), "=r"(d3) : "r"(addr));
}
__device__ __forceinline__ void mma16816(float* d, const uint32_t* a, const uint32_t* b) {
    asm volatile(
        "mma.sync.aligned.m16n8k16.row.col.f32.f16.f16.f32 "
        "{%0,%1,%2,%3}, {%4,%5,%6,%7}, {%8,%9}, {%0,%1,%2,%3};"
        : "+f"(d[0]), "+f"(d[1]), "+f"(d[2]), "+f"(d[3])
        : "r"(a[0]), "r"(a[1]), "r"(a[2]), "r"(a[3]), "r"(b[0]), "r"(b[1]));
}
#define BAR_SYNC(id)   asm volatile("bar.sync %0, %1;"   :: "r"(id), "n"(THREADS) : "memory")
#define BAR_ARRIVE(id) asm volatile("bar.arrive %0, %1;" :: "r"(id), "n"(THREADS) : "memory")

// ============================================================================
// Prep: W1eff^T = (C @ w1)^T -> fp16, per-64-chunk SW128-swizzled [n][k].
// ============================================================================
__global__ void prep_kernel(const float* __restrict__ conv_w, const float* __restrict__ w1) {
    int idx = blockIdx.x * blockDim.x + threadIdx.x;
    if (idx >= NCH * 128 * 64) return;
    int chunk = idx >> 13;
    int rem = idx & 8191;
    int n = rem >> 6;
    int kk = rem & 63;
    int k = chunk * 64 + kk;
    float v = 0.f;
    if (k < K_REAL) {
        int r = k / 28, c = k % 28;
        #pragma unroll
        for (int di = 0; di < 3; di++) {
            int oi = r - di;
            if (oi < 0 || oi > 25) continue;
            #pragma unroll
            for (int dj = 0; dj < 3; dj++) {
                int oj = c - dj;
                if (oj < 0 || oj > 25) continue;
                v += conv_w[di * 3 + dj] * w1[(oi * 26 + oj) * 128 + n];
            }
        }
    }
    uint32_t sw = sw128((uint32_t)(n * 128 + kk * 2));
    g_B[chunk][sw >> 1] = __float2half_rn(v);
}

// ============================================================================
// Main kernel. Consumers: wid 0-7, wm=(wid&1)*32, wn=(wid>>1)*32.
// Producers: wid 8-15 (ptid 0..255).
// ============================================================================
__global__ __launch_bounds__(THREADS, 1)
void digitconv_main(const float* __restrict__ x, const float* __restrict__ b1,
                    const float* __restrict__ w2, const float* __restrict__ b2,
                    float* __restrict__ out) {
    extern __shared__ char smem[];
    const uint32_t sbase = smem_u32(smem);
    const int tid = threadIdx.x;
    const int wid = tid >> 5;
    const int lane = tid & 31;
    const size_t m0 = (size_t)blockIdx.x * BM;

    float* b1s  = (float*)(smem + SM_B1);
    float* w2s  = (float*)(smem + SM_W2);
    float* pacc = (float*)(smem + SM_PACC);

    if (tid < 128) b1s[tid] = b1[tid];
    for (int i = tid; i < 1280; i += THREADS) w2s[i] = w2[i];
    for (int i = tid; i < BM * 10; i += THREADS) pacc[i] = 0.f;
    // pacc/b1s/w2s visibility to consumers: first FULL barrier trip covers all
    // 512 threads (producers arrive + consumers sync), acting as a full sync.

    if (wid >= 8) {
        // ======================= PRODUCER =======================
        const int ptid = tid - 256;
        float4 ah[2][4];

        auto ldgA = [&](int c, float4* dst) {
            #pragma unroll
            for (int q = 0; q < 4; q++) {
                int i = q * 256 + ptid;
                int row = i >> 4;
                int c4 = i & 15;
                int gcol = c * 64 + c4 * 4;
                if (gcol < K_REAL)
                    dst[q] = *reinterpret_cast<const float4*>(x + (m0 + row) * K_REAL + gcol);
                else
                    dst[q] = make_float4(0.f, 0.f, 0.f, 0.f);
            }
        };

        ldgA(0, ah[0]);

        #pragma unroll 1
        for (int c = 0; c < NCH; c++) {
            const int s = c & (NSTAGE - 1);
            const uint32_t st = sbase + (uint32_t)s * STAGE_BYTES;

            if (c + 1 < NCH) ldgA(c + 1, ah[(c + 1) & 1]);   // prefetch next chunk

            if (c >= NSTAGE) BAR_SYNC(EMPTY0 + s);            // stage s free?

            // B(c) -> stage s (L2-resident, pre-swizzled)
            {
                const char* gb = (const char*)&g_B[c][0];
                #pragma unroll
                for (int q = 0; q < 4; q++) {
                    int i = q * 256 + ptid;
                    cp_async16(st + B_OFF + i * 16, gb + i * 16);
                }
                asm volatile("cp.async.commit_group;" ::: "memory");
            }

            // A16(c) -> stage s
            {
                const float4* a = ah[c & 1];
                #pragma unroll
                for (int q = 0; q < 4; q++) {
                    int i = q * 256 + ptid;
                    int row = i >> 4;
                    int c4 = i & 15;
                    __half2 h0 = __floats2half2_rn(a[q].x, a[q].y);
                    __half2 h1 = __floats2half2_rn(a[q].z, a[q].w);
                    uint32_t w0 = *reinterpret_cast<uint32_t*>(&h0);
                    uint32_t w1r = *reinterpret_cast<uint32_t*>(&h1);
                    uint32_t dst = st + A16_OFF + sw128((uint32_t)(row * 128 + c4 * 8));
                    asm volatile("st.shared.v2.b32 [%0], {%1, %2};"
                                 :: "r"(dst), "r"(w0), "r"(w1r) : "memory");
                }
            }

            asm volatile("cp.async.wait_group 0;" ::: "memory");  // B(c) landed
            asm volatile("membar.cta;" ::: "memory");             // publish STS
            BAR_ARRIVE(FULL0 + s);                                // stage s full
        }
    } else {
        // ======================= CONSUMER =======================
        const int wm = (wid & 1) * 32;       // 2 m-groups of 32
        const int wn = (wid >> 1) * 32;      // 4 n-groups of 32
        const int sel = lane >> 3;

        float acc[2][4][4];
        #pragma unroll
        for (int tm = 0; tm < 2; tm++)
            #pragma unroll
            for (int tn = 0; tn < 4; tn++)
                #pragma unroll
                for (int e = 0; e < 4; e++) acc[tm][tn][e] = 0.f;

        #pragma unroll 1
        for (int c = 0; c < NCH; c++) {
            const int s = c & (NSTAGE - 1);
            const uint32_t st = sbase + (uint32_t)s * STAGE_BYTES;

            BAR_SYNC(FULL0 + s);             // wait stage s filled

            const uint32_t aB = st + A16_OFF;
            const uint32_t bB = st + B_OFF;
            #pragma unroll
            for (int ks = 0; ks < 4; ks++) {
                uint32_t afr[2][4];
                #pragma unroll
                for (int tm = 0; tm < 2; tm++) {
                    int r = wm + tm * 16 + (lane & 7) + ((sel & 1) << 3);
                    int kb = ks * 32 + ((sel >> 1) << 4);
                    ldmatrix_x4(afr[tm][0], afr[tm][1], afr[tm][2], afr[tm][3],
                                aB + sw128((uint32_t)(r * 128 + kb)));
                }
                uint32_t bf[4][2];
                #pragma unroll
                for (int tp = 0; tp < 2; tp++) {
                    int r = wn + (2 * tp + (sel >> 1)) * 8 + (lane & 7);
                    int kb = ks * 32 + ((sel & 1) << 4);
                    ldmatrix_x4(bf[2*tp][0], bf[2*tp][1], bf[2*tp+1][0], bf[2*tp+1][1],
                                bB + sw128((uint32_t)(r * 128 + kb)));
                }
                #pragma unroll
                for (int tm = 0; tm < 2; tm++)
                    #pragma unroll
                    for (int tn = 0; tn < 4; tn++)
                        mma16816(acc[tm][tn], afr[tm], bf[tn]);
            }

            BAR_ARRIVE(EMPTY0 + s);          // stage s consumed
        }

        // ---- Epilogue: relu(D + b1) @ w2, reduce into pacc ----
        #pragma unroll
        for (int tm = 0; tm < 2; tm++) {
            #pragma unroll
            for (int half = 0; half < 2; half++) {
                float p[10];
                #pragma unroll
                for (int j = 0; j < 10; j++) p[j] = 0.f;
                int r = wm + tm * 16 + (lane >> 2) + half * 8;
                #pragma unroll
                for (int tn = 0; tn < 4; tn++) {
                    #pragma unroll
                    for (int e = 0; e < 2; e++) {
                        int col = wn + tn * 8 + ((lane & 3) << 1) + e;
                        float v = acc[tm][tn][half * 2 + e] + b1s[col];
                        v = fmaxf(v, 0.f);
                        #pragma unroll
                        for (int j = 0; j < 10; j++) p[j] = fmaf(v, w2s[col * 10 + j], p[j]);
                    }
                }
                #pragma unroll
                for (int j = 0; j < 10; j++) {
                    p[j] += __shfl_xor_sync(0xFFFFFFFF, p[j], 1);
                    p[j] += __shfl_xor_sync(0xFFFFFFFF, p[j], 2);
                }
                if ((lane & 3) == 0) {
                    #pragma unroll
                    for (int j = 0; j < 10; j++) atomicAdd(&pacc[r * 10 + j], p[j]);
                }
            }
        }
    }

    __syncthreads();

    for (int i = tid; i < BM * 10; i += THREADS) {
        int r = i / 10, j = i - r * 10;
        out[(m0 + r) * 10 + j] = pacc[i] + __ldg(&b2[j]);
    }
}

// ============================================================================
extern "C" void kernel_launch(void* const* d_in, const int* in_sizes, int n_in,
                              void* d_out, int out_size) {
    const float* x      = (const float*)d_in[0];
    const float* conv_w = (const float*)d_in[1];
    const float* w1     = (const float*)d_in[2];
    const float* b1     = (const float*)d_in[3];
    const float* w2     = (const float*)d_in[4];
    const float* b2     = (const float*)d_in[5];
    float* out = (float*)d_out;

    cudaFuncSetAttribute(digitconv_main,
                         cudaFuncAttributeMaxDynamicSharedMemorySize, SMEM_TOTAL);

    prep_kernel<<<(NCH * 128 * 64 + 255) / 256, 256>>>(conv_w, w1);
    digitconv_main<<<B_ROWS / BM, THREADS, SMEM_TOTAL>>>(x, b1, w2, b2, out);
}

// round 14
// speedup vs baseline: 1.3581x; 1.3581x over previous
#include <cuda_runtime.h>
#include <cuda_fp16.h>
#include <cstdint>

// ============================================================================
// DigitConvolutionalModel: out = relu(conv3x3(x) @ w1 + b1) @ w2 + b2
// Folded:  out = relu(x @ W1eff + b1) @ w2 + b2,   W1eff = C @ w1   [784,128]
//
// R12: persistent CTAs (grid=148, 1/SM), W1eff fp16 fully RESIDENT in smem
// (13 x 16KB SW128 chunks = 208KB). Each CTA loops over M-tiles (BM=64),
// streaming only A: LDG->regs under MMA, STS into one 8KB A buffer.
// ============================================================================

#define B_ROWS   65536
#define K_REAL   784
#define NCH      13            // 13 * 64 = 832 >= 784 (chunk 12 zero-padded)
#define BM       64
#define NTILES   (B_ROWS / BM) // 1024
#define GRID     148
#define THREADS  256

// ---- dynamic smem layout ----
#define SM_BRES     0                       // 13 x 16384 = 212992
#define SM_A16      212992                  // 64x64 fp16 = 8192 (SW128)
#define SM_B1       221184                  // 128 fp32 = 512
#define SM_W2       221696                  // 1280 fp32 = 5120
#define SM_PACC     226816                  // 640 fp32 = 2560
#define SMEM_TOTAL  229376                  // 224 KB

// Pre-swizzled W1eff^T tiles: [chunk64][128n x 64k] fp16 (chunk 12 zero-padded).
__device__ __align__(16) __half g_B[NCH][128 * 64];

// -------------------- helpers --------------------
__device__ __forceinline__ uint32_t smem_u32(const void* p) {
    uint32_t a;
    asm("{ .reg .u64 t; cvta.to.shared.u64 t, %1; cvt.u32.u64 %0, t; }" : "=r"(a) : "l"(p));
    return a;
}
__device__ __forceinline__ uint32_t sw128(uint32_t off) {
    return off ^ ((off >> 3) & 0x70);
}
__device__ __forceinline__ void cp_async16(uint32_t dst, const void* src) {
    asm volatile("cp.async.cg.shared.global [%0], [%1], 16;" :: "r"(dst), "l"(src) : "memory");
}
__device__ __forceinline__ void ldmatrix_x4(uint32_t& d0, uint32_t& d1, uint32_t& d2,
                                            uint32_t& d3, uint32_t addr) {
    asm volatile("ldmatrix.sync.aligned.m8n8.x4.shared.b16 {%0,%1,%2,%3}, [%4];"
                 : "=r"(d0), "=r"(d1), "=r"(d2), "=r"(d3) : "r"(addr));
}
__device__ __forceinline__ void mma16816(float* d, const uint32_t* a, const uint32_t* b) {
    asm volatile(
        "mma.sync.aligned.m16n8k16.row.col.f32.f16.f16.f32 "
        "{%0,%1,%2,%3}, {%4,%5,%6,%7}, {%8,%9}, {%0,%1,%2,%3};"
        : "+f"(d[0]), "+f"(d[1]), "+f"(d[2]), "+f"(d[3])
        : "r"(a[0]), "r"(a[1]), "r"(a[2]), "r"(a[3]), "r"(b[0]), "r"(b[1]));
}

// ============================================================================
// Prep: W1eff^T = (C @ w1)^T -> fp16, per-64-chunk SW128-swizzled [n][k].
// ============================================================================
__global__ void prep_kernel(const float* __restrict__ conv_w, const float* __restrict__ w1) {
    int idx = blockIdx.x * blockDim.x + threadIdx.x;
    if (idx >= NCH * 128 * 64) return;
    int chunk = idx >> 13;
    int rem = idx & 8191;
    int n = rem >> 6;
    int kk = rem & 63;
    int k = chunk * 64 + kk;
    float v = 0.f;
    if (k < K_REAL) {
        int r = k / 28, c = k % 28;
        #pragma unroll
        for (int di = 0; di < 3; di++) {
            int oi = r - di;
            if (oi < 0 || oi > 25) continue;
            #pragma unroll
            for (int dj = 0; dj < 3; dj++) {
                int oj = c - dj;
                if (oj < 0 || oj > 25) continue;
                v += conv_w[di * 3 + dj] * w1[(oi * 26 + oj) * 128 + n];
            }
        }
    }
    uint32_t sw = sw128((uint32_t)(n * 128 + kk * 2));
    g_B[chunk][sw >> 1] = __float2half_rn(v);
}

// ============================================================================
// Main persistent kernel. 8 warps: wm=(wid&1)*32, wn=(wid>>1)*32 (m32 x n32).
// ============================================================================
__global__ __launch_bounds__(THREADS, 1)
void digitconv_main(const float* __restrict__ x, const float* __restrict__ b1,
                    const float* __restrict__ w2, const float* __restrict__ b2,
                    float* __restrict__ out) {
    extern __shared__ char smem[];
    const uint32_t sbase = smem_u32(smem);
    const int tid = threadIdx.x;
    const int wid = tid >> 5;
    const int lane = tid & 31;
    const int wm = (wid & 1) * 32;       // 2 m-groups of 32
    const int wn = (wid >> 1) * 32;      // 4 n-groups of 32
    const int sel = lane >> 3;

    float* b1s  = (float*)(smem + SM_B1);
    float* w2s  = (float*)(smem + SM_W2);
    float* pacc = (float*)(smem + SM_PACC);

    // ---- prologue: consts + resident B (208KB) via cp.async ----
    if (tid < 128) b1s[tid] = b1[tid];
    for (int i = tid; i < 1280; i += THREADS) w2s[i] = w2[i];
    for (int i = tid; i < BM * 10; i += THREADS) pacc[i] = 0.f;
    {
        const char* gb = (const char*)&g_B[0][0];     // 212992 contiguous bytes
        for (int i = tid; i < 212992 / 16; i += THREADS)
            cp_async16(sbase + SM_BRES + i * 16, gb + i * 16);
        asm volatile("cp.async.commit_group;" ::: "memory");
    }

    // per-thread A addressing: i = q*256+tid, row=i>>4 (0..63), c4=i&15
    float4 areg[4];
    auto ldgA = [&](int t, int c) {
        const size_t m0 = (size_t)t * BM;
        #pragma unroll
        for (int q = 0; q < 4; q++) {
            int i = q * THREADS + tid;
            int row = i >> 4;
            int c4 = i & 15;
            int gcol = c * 64 + c4 * 4;
            if (gcol < K_REAL)
                areg[q] = *reinterpret_cast<const float4*>(x + (m0 + row) * K_REAL + gcol);
            else
                areg[q] = make_float4(0.f, 0.f, 0.f, 0.f);
        }
    };
    auto stsA = [&]() {
        #pragma unroll
        for (int q = 0; q < 4; q++) {
            int i = q * THREADS + tid;
            int row = i >> 4;
            int c4 = i & 15;
            __half2 h0 = __floats2half2_rn(areg[q].x, areg[q].y);
            __half2 h1 = __floats2half2_rn(areg[q].z, areg[q].w);
            uint32_t w0 = *reinterpret_cast<uint32_t*>(&h0);
            uint32_t w1r = *reinterpret_cast<uint32_t*>(&h1);
            uint32_t dst = sbase + SM_A16 + sw128((uint32_t)(row * 128 + c4 * 8));
            asm volatile("st.shared.v2.b32 [%0], {%1, %2};" :: "r"(dst), "r"(w0), "r"(w1r)
                         : "memory");
        }
    };

    const int t0 = blockIdx.x;
    ldgA(t0, 0);                                     // first A chunk in flight

    asm volatile("cp.async.wait_group 0;" ::: "memory");
    __syncthreads();                                  // B resident + consts ready

    const uint32_t aB = sbase + SM_A16;

    #pragma unroll 1
    for (int t = t0; t < NTILES; t += GRID) {
        float acc[2][4][4];
        #pragma unroll
        for (int tm = 0; tm < 2; tm++)
            #pragma unroll
            for (int tn = 0; tn < 4; tn++)
                #pragma unroll
                for (int e = 0; e < 4; e++) acc[tm][tn][e] = 0.f;

        #pragma unroll 1
        for (int c = 0; c < NCH; c++) {
            __syncthreads();                  // previous MMA done with A buffer
            stsA();                           // A16(c)
            __syncthreads();                  // A buffer ready

            if (c + 1 < NCH) ldgA(t, c + 1);          // next chunk under MMA
            else if (t + GRID < NTILES) ldgA(t + GRID, 0);   // next tile's chunk 0

            const uint32_t bB = sbase + SM_BRES + (uint32_t)c * 16384;
            #pragma unroll
            for (int ks = 0; ks < 4; ks++) {
                uint32_t afr[2][4];
                #pragma unroll
                for (int tm = 0; tm < 2; tm++) {
                    int r = wm + tm * 16 + (lane & 7) + ((sel & 1) << 3);
                    int kb = ks * 32 + ((sel >> 1) << 4);
                    ldmatrix_x4(afr[tm][0], afr[tm][1], afr[tm][2], afr[tm][3],
                                aB + sw128((uint32_t)(r * 128 + kb)));
                }
                uint32_t bf[4][2];
                #pragma unroll
                for (int tp = 0; tp < 2; tp++) {
                    int r = wn + (2 * tp + (sel >> 1)) * 8 + (lane & 7);
                    int kb = ks * 32 + ((sel & 1) << 4);
                    ldmatrix_x4(bf[2*tp][0], bf[2*tp][1], bf[2*tp+1][0], bf[2*tp+1][1],
                                bB + sw128((uint32_t)(r * 128 + kb)));
                }
                #pragma unroll
                for (int tm = 0; tm < 2; tm++)
                    #pragma unroll
                    for (int tn = 0; tn < 4; tn++)
                        mma16816(acc[tm][tn], afr[tm], bf[tn]);
            }
        }

        // ---- Epilogue: relu(D + b1) @ w2, reduce, + b2, store ----
        #pragma unroll
        for (int tm = 0; tm < 2; tm++) {
            #pragma unroll
            for (int half = 0; half < 2; half++) {
                float p[10];
                #pragma unroll
                for (int j = 0; j < 10; j++) p[j] = 0.f;
                int r = wm + tm * 16 + (lane >> 2) + half * 8;
                #pragma unroll
                for (int tn = 0; tn < 4; tn++) {
                    #pragma unroll
                    for (int e = 0; e < 2; e++) {
                        int col = wn + tn * 8 + ((lane & 3) << 1) + e;
                        float v = acc[tm][tn][half * 2 + e] + b1s[col];
                        v = fmaxf(v, 0.f);
                        #pragma unroll
                        for (int j = 0; j < 10; j++) p[j] = fmaf(v, w2s[col * 10 + j], p[j]);
                    }
                }
                #pragma unroll
                for (int j = 0; j < 10; j++) {
                    p[j] += __shfl_xor_sync(0xFFFFFFFF, p[j], 1);
                    p[j] += __shfl_xor_sync(0xFFFFFFFF, p[j], 2);
                }
                if ((lane & 3) == 0) {
                    #pragma unroll
                    for (int j = 0; j < 10; j++) atomicAdd(&pacc[r * 10 + j], p[j]);
                }
            }
        }
        __syncthreads();

        const size_t m0 = (size_t)t * BM;
        for (int i = tid; i < BM * 10; i += THREADS) {
            int r = i / 10, j = i - r * 10;
            out[(m0 + r) * 10 + j] = pacc[i] + __ldg(&b2[j]);
            pacc[i] = 0.f;                    // re-zero own element for next tile
        }
        // next tile's first chunk-loop __syncthreads() orders pacc re-zero
        // before any new epilogue atomics.
    }
}

// ============================================================================
extern "C" void kernel_launch(void* const* d_in, const int* in_sizes, int n_in,
                              void* d_out, int out_size) {
    const float* x      = (const float*)d_in[0];
    const float* conv_w = (const float*)d_in[1];
    const float* w1     = (const float*)d_in[2];
    const float* b1     = (const float*)d_in[3];
    const float* w2     = (const float*)d_in[4];
    const float* b2     = (const float*)d_in[5];
    float* out = (float*)d_out;

    cudaFuncSetAttribute(digitconv_main,
                         cudaFuncAttributeMaxDynamicSharedMemorySize, SMEM_TOTAL);

    prep_kernel<<<(NCH * 128 * 64 + 255) / 256, 256>>>(conv_w, w1);
    digitconv_main<<<GRID, THREADS, SMEM_TOTAL>>>(x, b1, w2, b2, out);
}